// round 12
// baseline (speedup 1.0000x reference)
#include <cuda_runtime.h>
#include <cuda_bf16.h>
#include <cstdint>

#define DIM 256
#define NBINS 32
#define CT 32            // columns per tile
#define MINW 1e-3f
#define MINH 1e-3f
#define MIND 1e-3f

// Precomputed per-(dim,bin) tables, split into float2 to reduce LDS bank conflicts
__device__ float2 g_p0[DIM * NBINS];   // {cw_lo, 1/w}
__device__ float2 g_p1[DIM * NBINS];   // {ch_lo, h}
__device__ float2 g_p2[DIM * NBINS];   // {d0, d1}

__device__ __forceinline__ float softplus_min(float v) {
    float sp = (v > 15.f) ? v : log1pf(expf(v));
    return MIND + sp;
}

// One warp per dim: softmax -> floor -> cumsum for widths & heights, derivatives.
__global__ void spline_precompute_kernel(const float* __restrict__ width,
                                         const float* __restrict__ height,
                                         const float* __restrict__ deriv) {
    int d = blockIdx.x;
    int t = threadIdx.x;   // 0..31

    // ---- widths ----
    float wv = width[d * NBINS + t];
    float m = wv;
    #pragma unroll
    for (int o = 16; o; o >>= 1) m = fmaxf(m, __shfl_xor_sync(0xFFFFFFFFu, m, o));
    float e = __expf(wv - m);
    float s = e;
    #pragma unroll
    for (int o = 16; o; o >>= 1) s += __shfl_xor_sync(0xFFFFFFFFu, s, o);
    float sz = MINW + (1.f - NBINS * MINW) * (e / s);
    float incl = sz;
    #pragma unroll
    for (int o = 1; o < 32; o <<= 1) {
        float v = __shfl_up_sync(0xFFFFFFFFu, incl, o);
        if (t >= o) incl += v;
    }
    float cw_hi = (t == 31) ? 1.f : incl;
    float up = __shfl_up_sync(0xFFFFFFFFu, incl, 1);
    float cw_lo = (t == 0) ? 0.f : up;
    float w = cw_hi - cw_lo;

    // ---- heights ----
    float hv = height[d * NBINS + t];
    float mh = hv;
    #pragma unroll
    for (int o = 16; o; o >>= 1) mh = fmaxf(mh, __shfl_xor_sync(0xFFFFFFFFu, mh, o));
    float eh = __expf(hv - mh);
    float sh = eh;
    #pragma unroll
    for (int o = 16; o; o >>= 1) sh += __shfl_xor_sync(0xFFFFFFFFu, sh, o);
    float szh = MINH + (1.f - NBINS * MINH) * (eh / sh);
    float inclh = szh;
    #pragma unroll
    for (int o = 1; o < 32; o <<= 1) {
        float v = __shfl_up_sync(0xFFFFFFFFu, inclh, o);
        if (t >= o) inclh += v;
    }
    float ch_hi = (t == 31) ? 1.f : inclh;
    float uph = __shfl_up_sync(0xFFFFFFFFu, inclh, 1);
    float ch_lo = (t == 0) ? 0.f : uph;
    float h = ch_hi - ch_lo;

    // ---- derivatives (boundary == 1 exactly) ----
    float d0 = (t == 0)  ? 1.f : softplus_min(deriv[d * (NBINS - 1) + t - 1]);
    float d1 = (t == 31) ? 1.f : softplus_min(deriv[d * (NBINS - 1) + t]);

    float invw = 1.f / w;

    g_p0[d * NBINS + t] = make_float2(cw_lo, invw);
    g_p1[d * NBINS + t] = make_float2(ch_lo, h);
    g_p2[d * NBINS + t] = make_float2(d0, d1);
}

// Main kernel: branch-free bin lookup (guess + 2 unconditional correction steps
// + uniformly-false safety loop), tables in smem as three float2 arrays.
__global__ void __launch_bounds__(256, 8)
spline_main_kernel(const float* __restrict__ x, float* __restrict__ out, int B) {
    __shared__ float2 s_p0[CT * NBINS];   // 8 KB {cw_lo, invw}
    __shared__ float2 s_p1[CT * NBINS];   // 8 KB {ch_lo, h}
    __shared__ float2 s_p2[CT * NBINS];   // 8 KB {d0, d1}

    const int colBase = blockIdx.y * CT;
    const int tid = threadIdx.x;

    for (int i = tid; i < CT * NBINS; i += 256) {
        s_p0[i] = g_p0[colBase * NBINS + i];
        s_p1[i] = g_p1[colBase * NBINS + i];
        s_p2[i] = g_p2[colBase * NBINS + i];
    }
    __syncthreads();

    const int cg   = tid & 7;     // colgroup 0..7 (4 cols each)
    const int rown = tid >> 3;    // 0..31
    const int lc0  = cg * 4;
    const int colOff = colBase + lc0;

    float* __restrict__ outY = out;
    float* __restrict__ outL = out + (size_t)B * DIM;

    for (int row = blockIdx.x * 32 + rown; row < B; row += gridDim.x * 32) {
        const float4 xv = *(const float4*)(x + (size_t)row * DIM + colOff);
        float yv[4], lv[4];
        #pragma unroll
        for (int k = 0; k < 4; k++) {
            const int lc = lc0 + k;
            const float2* __restrict__ col0 = s_p0 + lc * NBINS;
            float xs = (k == 0) ? xv.x : (k == 1) ? xv.y : (k == 2) ? xv.z : xv.w;
            float xc = __saturatef(xs);

            // guess
            int b = __float2int_rd(xc * 32.f);
            b = min(b, NBINS - 1);
            float2 p0 = col0[b];
            float theta = (xc - p0.x) * p0.y;

            // 2 unconditional branch-free correction steps
            #pragma unroll
            for (int it = 0; it < 2; ++it) {
                int step = (theta >= 1.f ? 1 : 0) - (theta < 0.f ? 1 : 0);
                b = min(max(b + step, 0), NBINS - 1);
                p0 = col0[b];
                theta = (xc - p0.x) * p0.y;
            }
            // safety loop: uniformly false for essentially all warps
            while ((theta < 0.f && b > 0) || (theta >= 1.f && b < NBINS - 1)) {
                b += (theta >= 1.f) ? 1 : -1;
                p0 = col0[b];
                theta = (xc - p0.x) * p0.y;
            }

            const float2 p1 = s_p1[lc * NBINS + b];
            const float2 p2 = s_p2[lc * NBINS + b];

            float omt    = 1.f - theta;
            float t1m    = theta * omt;
            float th2    = theta * theta;
            float h      = p1.y;
            float delta  = h * p0.y;        // h * invw
            float delta2 = delta * delta;
            float dd0 = p2.x, dd1 = p2.y;

            float num  = h * fmaf(delta, th2, dd0 * t1m);
            float den  = fmaf(dd0 + dd1 - 2.f * delta, t1m, delta);
            float rden = __fdividef(1.f, den);
            float yin  = fmaf(num, rden, p1.x);

            float dnum = delta2 * fmaf(dd1, th2, fmaf(2.f * delta, t1m, dd0 * omt * omt));
            float lin  = __logf(dnum * rden * rden);

            bool inside = (xs >= 0.f) && (xs <= 1.f);
            yv[k] = inside ? yin : xs;
            lv[k] = inside ? lin : 0.f;
        }
        *(float4*)(outY + (size_t)row * DIM + colOff) = make_float4(yv[0], yv[1], yv[2], yv[3]);
        *(float4*)(outL + (size_t)row * DIM + colOff) = make_float4(lv[0], lv[1], lv[2], lv[3]);
    }
}

extern "C" void kernel_launch(void* const* d_in, const int* in_sizes, int n_in,
                              void* d_out, int out_size) {
    const float* x      = (const float*)d_in[0];
    const float* width  = (const float*)d_in[1];
    const float* height = (const float*)d_in[2];
    const float* deriv  = (const float*)d_in[3];
    float* out = (float*)d_out;

    const int B = in_sizes[0] / DIM;

    spline_precompute_kernel<<<DIM, 32>>>(width, height, deriv);

    dim3 grid(148, DIM / CT);   // 1184 blocks = 148 SMs x 8 blocks (full thread wave)
    spline_main_kernel<<<grid, 256>>>(x, out, B);
}

// round 13
// speedup vs baseline: 1.1054x; 1.1054x over previous
#include <cuda_runtime.h>
#include <cuda_bf16.h>
#include <cstdint>

#define DIM 256
#define NBINS 32
#define CT 32            // columns per tile
#define MINW 1e-3f
#define MINH 1e-3f
#define MIND 1e-3f

// Precomputed per-(dim,bin) tables
__device__ float2 g_p0[DIM * NBINS];   // {cw_lo, 1/w}   (search table)
__device__ float4 g_pC[DIM * NBINS];   // {ch_lo, h, d0, d1}

__device__ __forceinline__ float softplus_min(float v) {
    float sp = (v > 15.f) ? v : log1pf(expf(v));
    return MIND + sp;
}

// One warp per dim: softmax -> floor -> cumsum for widths & heights, derivatives.
__global__ void spline_precompute_kernel(const float* __restrict__ width,
                                         const float* __restrict__ height,
                                         const float* __restrict__ deriv) {
    int d = blockIdx.x;
    int t = threadIdx.x;   // 0..31

    // ---- widths ----
    float wv = width[d * NBINS + t];
    float m = wv;
    #pragma unroll
    for (int o = 16; o; o >>= 1) m = fmaxf(m, __shfl_xor_sync(0xFFFFFFFFu, m, o));
    float e = __expf(wv - m);
    float s = e;
    #pragma unroll
    for (int o = 16; o; o >>= 1) s += __shfl_xor_sync(0xFFFFFFFFu, s, o);
    float sz = MINW + (1.f - NBINS * MINW) * (e / s);
    float incl = sz;
    #pragma unroll
    for (int o = 1; o < 32; o <<= 1) {
        float v = __shfl_up_sync(0xFFFFFFFFu, incl, o);
        if (t >= o) incl += v;
    }
    float cw_hi = (t == 31) ? 1.f : incl;
    float up = __shfl_up_sync(0xFFFFFFFFu, incl, 1);
    float cw_lo = (t == 0) ? 0.f : up;
    float w = cw_hi - cw_lo;

    // ---- heights ----
    float hv = height[d * NBINS + t];
    float mh = hv;
    #pragma unroll
    for (int o = 16; o; o >>= 1) mh = fmaxf(mh, __shfl_xor_sync(0xFFFFFFFFu, mh, o));
    float eh = __expf(hv - mh);
    float sh = eh;
    #pragma unroll
    for (int o = 16; o; o >>= 1) sh += __shfl_xor_sync(0xFFFFFFFFu, sh, o);
    float szh = MINH + (1.f - NBINS * MINH) * (eh / sh);
    float inclh = szh;
    #pragma unroll
    for (int o = 1; o < 32; o <<= 1) {
        float v = __shfl_up_sync(0xFFFFFFFFu, inclh, o);
        if (t >= o) inclh += v;
    }
    float ch_hi = (t == 31) ? 1.f : inclh;
    float uph = __shfl_up_sync(0xFFFFFFFFu, inclh, 1);
    float ch_lo = (t == 0) ? 0.f : uph;
    float h = ch_hi - ch_lo;

    // ---- derivatives (boundary == 1 exactly) ----
    float d0 = (t == 0)  ? 1.f : softplus_min(deriv[d * (NBINS - 1) + t - 1]);
    float d1 = (t == 31) ? 1.f : softplus_min(deriv[d * (NBINS - 1) + t]);

    float invw = 1.f / w;

    g_p0[d * NBINS + t] = make_float2(cw_lo, invw);
    g_pC[d * NBINS + t] = make_float4(ch_lo, h, d0, d1);
}

// Main kernel: each block owns a 32-column tile; tables live in smem.
// Search on 8B {cw_lo,invw} with single divergent retry loop; then one
// LDS.128 gather of {ch_lo, h, d0, d1}.
__global__ void __launch_bounds__(256, 8)
spline_main_kernel(const float* __restrict__ x, float* __restrict__ out, int B) {
    __shared__ float2 s_p0[CT * NBINS];   //  8 KB {cw_lo, invw}
    __shared__ float4 s_pC[CT * NBINS];   // 16 KB {ch_lo, h, d0, d1}

    const int colBase = blockIdx.y * CT;
    const int tid = threadIdx.x;

    for (int i = tid; i < CT * NBINS; i += 256) {
        s_p0[i] = g_p0[colBase * NBINS + i];
        s_pC[i] = g_pC[colBase * NBINS + i];
    }
    __syncthreads();

    const int cg   = tid & 7;     // colgroup 0..7 (4 cols each)
    const int rown = tid >> 3;    // 0..31
    const int lc0  = cg * 4;
    const int colOff = colBase + lc0;

    float* __restrict__ outY = out;
    float* __restrict__ outL = out + (size_t)B * DIM;

    for (int row = blockIdx.x * 32 + rown; row < B; row += gridDim.x * 32) {
        const float4 xv = *(const float4*)(x + (size_t)row * DIM + colOff);
        float yv[4], lv[4];
        #pragma unroll
        for (int k = 0; k < 4; k++) {
            const int lc = lc0 + k;
            const float2* __restrict__ col0 = s_p0 + lc * NBINS;
            float xs = (k == 0) ? xv.x : (k == 1) ? xv.y : (k == 2) ? xv.z : xv.w;
            float xc = __saturatef(xs);

            // uniform guess + single divergent retry loop (few lanes active)
            int b = __float2int_rd(xc * 32.f);
            b = min(b, NBINS - 1);
            float2 p0 = col0[b];
            float theta = (xc - p0.x) * p0.y;
            while ((theta < 0.f && b > 0) || (theta >= 1.f && b < NBINS - 1)) {
                b += (theta >= 1.f) ? 1 : -1;
                p0 = col0[b];
                theta = (xc - p0.x) * p0.y;
            }

            const float4 pc = s_pC[lc * NBINS + b];

            float omt    = 1.f - theta;
            float t1m    = theta * omt;
            float th2    = theta * theta;
            float h      = pc.y;
            float delta  = h * p0.y;        // h * invw
            float delta2 = delta * delta;
            float dd0 = pc.z, dd1 = pc.w;

            float num  = h * fmaf(delta, th2, dd0 * t1m);
            float den  = fmaf(dd0 + dd1 - 2.f * delta, t1m, delta);
            float rden = __fdividef(1.f, den);
            float yin  = fmaf(num, rden, pc.x);

            float dnum = delta2 * fmaf(dd1, th2, fmaf(2.f * delta, t1m, dd0 * omt * omt));
            float lin  = __logf(dnum * rden * rden);

            bool inside = (xs >= 0.f) && (xs <= 1.f);
            yv[k] = inside ? yin : xs;
            lv[k] = inside ? lin : 0.f;
        }
        *(float4*)(outY + (size_t)row * DIM + colOff) = make_float4(yv[0], yv[1], yv[2], yv[3]);
        *(float4*)(outL + (size_t)row * DIM + colOff) = make_float4(lv[0], lv[1], lv[2], lv[3]);
    }
}

extern "C" void kernel_launch(void* const* d_in, const int* in_sizes, int n_in,
                              void* d_out, int out_size) {
    const float* x      = (const float*)d_in[0];
    const float* width  = (const float*)d_in[1];
    const float* height = (const float*)d_in[2];
    const float* deriv  = (const float*)d_in[3];
    float* out = (float*)d_out;

    const int B = in_sizes[0] / DIM;

    spline_precompute_kernel<<<DIM, 32>>>(width, height, deriv);

    dim3 grid(148, DIM / CT);   // 1184 blocks = 148 SMs x 8 blocks (full thread wave)
    spline_main_kernel<<<grid, 256>>>(x, out, B);
}

// round 14
// speedup vs baseline: 1.2625x; 1.1422x over previous
#include <cuda_runtime.h>
#include <cuda_bf16.h>
#include <cstdint>

#define DIM 256
#define NBINS 32
#define CT 32            // columns per tile
#define CSTRIDE 33       // padded column stride (breaks bank alignment)
#define MINW 1e-3f
#define MINH 1e-3f
#define MIND 1e-3f

// Precomputed per-(dim,bin) tables (dense in gmem)
__device__ float2 g_p0[DIM * NBINS];   // {cw_lo, 1/w}
__device__ float2 g_p1[DIM * NBINS];   // {ch_lo, h}
__device__ float2 g_p2[DIM * NBINS];   // {d0, d1}

__device__ __forceinline__ float softplus_min(float v) {
    float sp = (v > 15.f) ? v : log1pf(expf(v));
    return MIND + sp;
}

// One warp per dim: softmax -> floor -> cumsum for widths & heights, derivatives.
__global__ void spline_precompute_kernel(const float* __restrict__ width,
                                         const float* __restrict__ height,
                                         const float* __restrict__ deriv) {
    int d = blockIdx.x;
    int t = threadIdx.x;   // 0..31

    // ---- widths ----
    float wv = width[d * NBINS + t];
    float m = wv;
    #pragma unroll
    for (int o = 16; o; o >>= 1) m = fmaxf(m, __shfl_xor_sync(0xFFFFFFFFu, m, o));
    float e = __expf(wv - m);
    float s = e;
    #pragma unroll
    for (int o = 16; o; o >>= 1) s += __shfl_xor_sync(0xFFFFFFFFu, s, o);
    float sz = MINW + (1.f - NBINS * MINW) * (e / s);
    float incl = sz;
    #pragma unroll
    for (int o = 1; o < 32; o <<= 1) {
        float v = __shfl_up_sync(0xFFFFFFFFu, incl, o);
        if (t >= o) incl += v;
    }
    float cw_hi = (t == 31) ? 1.f : incl;
    float up = __shfl_up_sync(0xFFFFFFFFu, incl, 1);
    float cw_lo = (t == 0) ? 0.f : up;
    float w = cw_hi - cw_lo;

    // ---- heights ----
    float hv = height[d * NBINS + t];
    float mh = hv;
    #pragma unroll
    for (int o = 16; o; o >>= 1) mh = fmaxf(mh, __shfl_xor_sync(0xFFFFFFFFu, mh, o));
    float eh = __expf(hv - mh);
    float sh = eh;
    #pragma unroll
    for (int o = 16; o; o >>= 1) sh += __shfl_xor_sync(0xFFFFFFFFu, sh, o);
    float szh = MINH + (1.f - NBINS * MINH) * (eh / sh);
    float inclh = szh;
    #pragma unroll
    for (int o = 1; o < 32; o <<= 1) {
        float v = __shfl_up_sync(0xFFFFFFFFu, inclh, o);
        if (t >= o) inclh += v;
    }
    float ch_hi = (t == 31) ? 1.f : inclh;
    float uph = __shfl_up_sync(0xFFFFFFFFu, inclh, 1);
    float ch_lo = (t == 0) ? 0.f : uph;
    float h = ch_hi - ch_lo;

    // ---- derivatives (boundary == 1 exactly) ----
    float d0 = (t == 0)  ? 1.f : softplus_min(deriv[d * (NBINS - 1) + t - 1]);
    float d1 = (t == 31) ? 1.f : softplus_min(deriv[d * (NBINS - 1) + t]);

    float invw = 1.f / w;

    g_p0[d * NBINS + t] = make_float2(cw_lo, invw);
    g_p1[d * NBINS + t] = make_float2(ch_lo, h);
    g_p2[d * NBINS + t] = make_float2(d0, d1);
}

// Main kernel: each block owns a 32-column tile; tables live in smem as three
// float2 arrays with padded column stride 33 (banks = 2*lc + 2*b mod 32,
// spreading the warp's 8 columns across bank-pair offsets).
__global__ void __launch_bounds__(256, 8)
spline_main_kernel(const float* __restrict__ x, float* __restrict__ out, int B) {
    __shared__ float2 s_p0[CT * CSTRIDE];   // {cw_lo, invw}
    __shared__ float2 s_p1[CT * CSTRIDE];   // {ch_lo, h}
    __shared__ float2 s_p2[CT * CSTRIDE];   // {d0, d1}

    const int colBase = blockIdx.y * CT;
    const int tid = threadIdx.x;

    for (int i = tid; i < CT * NBINS; i += 256) {
        const int lc = i >> 5;          // i / NBINS
        const int bb = i & 31;          // i % NBINS
        const int si = lc * CSTRIDE + bb;
        s_p0[si] = g_p0[colBase * NBINS + i];
        s_p1[si] = g_p1[colBase * NBINS + i];
        s_p2[si] = g_p2[colBase * NBINS + i];
    }
    __syncthreads();

    const int cg   = tid & 7;     // colgroup 0..7 (4 cols each)
    const int rown = tid >> 3;    // 0..31
    const int lc0  = cg * 4;
    const int colOff = colBase + lc0;

    float* __restrict__ outY = out;
    float* __restrict__ outL = out + B * DIM;   // 16.7M < 2^31, int ok

    const int startRow = blockIdx.x * 32 + rown;
    const int stride   = gridDim.x * 32;
    int idx = startRow * DIM + colOff;
    const int idxStep = stride * DIM;

    for (int row = startRow; row < B; row += stride, idx += idxStep) {
        const float4 xv = *(const float4*)(x + idx);
        float yv[4], lv[4];
        #pragma unroll
        for (int k = 0; k < 4; k++) {
            const int lc = lc0 + k;
            const float2* __restrict__ col0 = s_p0 + lc * CSTRIDE;
            float xs = (k == 0) ? xv.x : (k == 1) ? xv.y : (k == 2) ? xv.z : xv.w;
            float xc = __saturatef(xs);

            // uniform guess + retry using cw_lo/invw from the gathered params
            int b = __float2int_rd(xc * 32.f);
            b = min(b, NBINS - 1);
            float2 p0 = col0[b];
            float theta = (xc - p0.x) * p0.y;
            while (theta < 0.f && b > 0) {
                --b; p0 = col0[b]; theta = (xc - p0.x) * p0.y;
            }
            while (theta >= 1.f && b < NBINS - 1) {
                ++b; p0 = col0[b]; theta = (xc - p0.x) * p0.y;
            }

            const float2 p1 = s_p1[lc * CSTRIDE + b];
            const float2 p2 = s_p2[lc * CSTRIDE + b];

            float omt    = 1.f - theta;
            float t1m    = theta * omt;
            float th2    = theta * theta;
            float h      = p1.y;
            float delta  = h * p0.y;        // h * invw
            float delta2 = delta * delta;
            float dd0 = p2.x, dd1 = p2.y;

            float num  = h * fmaf(delta, th2, dd0 * t1m);
            float den  = fmaf(dd0 + dd1 - 2.f * delta, t1m, delta);
            float rden = __fdividef(1.f, den);
            float yin  = fmaf(num, rden, p1.x);

            float dnum = delta2 * fmaf(dd1, th2, fmaf(2.f * delta, t1m, dd0 * omt * omt));
            float lin  = __logf(dnum * rden * rden);

            bool inside = (xs >= 0.f) && (xs <= 1.f);
            yv[k] = inside ? yin : xs;
            lv[k] = inside ? lin : 0.f;
        }
        *(float4*)(outY + idx) = make_float4(yv[0], yv[1], yv[2], yv[3]);
        *(float4*)(outL + idx) = make_float4(lv[0], lv[1], lv[2], lv[3]);
    }
}

extern "C" void kernel_launch(void* const* d_in, const int* in_sizes, int n_in,
                              void* d_out, int out_size) {
    const float* x      = (const float*)d_in[0];
    const float* width  = (const float*)d_in[1];
    const float* height = (const float*)d_in[2];
    const float* deriv  = (const float*)d_in[3];
    float* out = (float*)d_out;

    const int B = in_sizes[0] / DIM;

    spline_precompute_kernel<<<DIM, 32>>>(width, height, deriv);

    dim3 grid(148, DIM / CT);   // 1184 blocks = 148 SMs x 8 blocks (full thread wave)
    spline_main_kernel<<<grid, 256>>>(x, out, B);
}

// round 15
// speedup vs baseline: 1.3114x; 1.0387x over previous
#include <cuda_runtime.h>
#include <cuda_bf16.h>
#include <cstdint>

#define DIM 256
#define NBINS 32
#define CT 32            // columns per tile
#define CSTRIDE 33       // padded column stride
#define MINW 1e-3f
#define MINH 1e-3f
#define MIND 1e-3f

// Precomputed per-(dim,bin) tables (dense in gmem)
__device__ float2 g_p0[DIM * NBINS];   // {cw_lo, 1/w}   (search table)
__device__ float4 g_pC[DIM * NBINS];   // {ch_lo, h, d0, d1}

__device__ __forceinline__ float softplus_min(float v) {
    float sp = (v > 15.f) ? v : log1pf(expf(v));
    return MIND + sp;
}

// 64 blocks x 128 threads; each warp handles one dim.
__global__ void spline_precompute_kernel(const float* __restrict__ width,
                                         const float* __restrict__ height,
                                         const float* __restrict__ deriv) {
    int d = blockIdx.x * 4 + (threadIdx.x >> 5);
    int t = threadIdx.x & 31;   // lane

    // ---- widths ----
    float wv = width[d * NBINS + t];
    float m = wv;
    #pragma unroll
    for (int o = 16; o; o >>= 1) m = fmaxf(m, __shfl_xor_sync(0xFFFFFFFFu, m, o));
    float e = __expf(wv - m);
    float s = e;
    #pragma unroll
    for (int o = 16; o; o >>= 1) s += __shfl_xor_sync(0xFFFFFFFFu, s, o);
    float sz = MINW + (1.f - NBINS * MINW) * (e / s);
    float incl = sz;
    #pragma unroll
    for (int o = 1; o < 32; o <<= 1) {
        float v = __shfl_up_sync(0xFFFFFFFFu, incl, o);
        if (t >= o) incl += v;
    }
    float cw_hi = (t == 31) ? 1.f : incl;
    float up = __shfl_up_sync(0xFFFFFFFFu, incl, 1);
    float cw_lo = (t == 0) ? 0.f : up;
    float w = cw_hi - cw_lo;

    // ---- heights ----
    float hv = height[d * NBINS + t];
    float mh = hv;
    #pragma unroll
    for (int o = 16; o; o >>= 1) mh = fmaxf(mh, __shfl_xor_sync(0xFFFFFFFFu, mh, o));
    float eh = __expf(hv - mh);
    float sh = eh;
    #pragma unroll
    for (int o = 16; o; o >>= 1) sh += __shfl_xor_sync(0xFFFFFFFFu, sh, o);
    float szh = MINH + (1.f - NBINS * MINH) * (eh / sh);
    float inclh = szh;
    #pragma unroll
    for (int o = 1; o < 32; o <<= 1) {
        float v = __shfl_up_sync(0xFFFFFFFFu, inclh, o);
        if (t >= o) inclh += v;
    }
    float ch_hi = (t == 31) ? 1.f : inclh;
    float uph = __shfl_up_sync(0xFFFFFFFFu, inclh, 1);
    float ch_lo = (t == 0) ? 0.f : uph;
    float h = ch_hi - ch_lo;

    // ---- derivatives (boundary == 1 exactly) ----
    float sp = (t < NBINS - 1) ? softplus_min(deriv[d * (NBINS - 1) + t]) : 1.f;
    float d1 = (t == NBINS - 1) ? 1.f : sp;
    float spp = __shfl_up_sync(0xFFFFFFFFu, sp, 1);
    float d0 = (t == 0) ? 1.f : spp;

    float invw = 1.f / w;

    g_p0[d * NBINS + t] = make_float2(cw_lo, invw);
    g_pC[d * NBINS + t] = make_float4(ch_lo, h, d0, d1);
}

// Main kernel: each block owns a 32-column tile.
// Search on padded 8B {cw_lo,invw} with the two simple divergent retry loops;
// then ONE LDS.128 gather of {ch_lo, h, d0, d1}.
__global__ void __launch_bounds__(256, 8)
spline_main_kernel(const float* __restrict__ x, float* __restrict__ out, int B) {
    __shared__ float2 s_p0[CT * CSTRIDE];   // ~8.25 KB {cw_lo, invw}
    __shared__ float4 s_pC[CT * CSTRIDE];   // ~16.5 KB {ch_lo, h, d0, d1}

    const int colBase = blockIdx.y * CT;
    const int tid = threadIdx.x;

    for (int i = tid; i < CT * NBINS; i += 256) {
        const int lc = i >> 5;
        const int bb = i & 31;
        const int si = lc * CSTRIDE + bb;
        s_p0[si] = g_p0[colBase * NBINS + i];
        s_pC[si] = g_pC[colBase * NBINS + i];
    }
    __syncthreads();

    const int cg   = tid & 7;     // colgroup 0..7 (4 cols each)
    const int rown = tid >> 3;    // 0..31
    const int lc0  = cg * 4;
    const int colOff = colBase + lc0;

    float* __restrict__ outY = out;
    float* __restrict__ outL = out + B * DIM;   // 16.7M < 2^31, int ok

    const int startRow = blockIdx.x * 32 + rown;
    const int stride   = gridDim.x * 32;
    int idx = startRow * DIM + colOff;
    const int idxStep = stride * DIM;

    for (int row = startRow; row < B; row += stride, idx += idxStep) {
        const float4 xv = *(const float4*)(x + idx);
        float yv[4], lv[4];
        #pragma unroll
        for (int k = 0; k < 4; k++) {
            const int lc = lc0 + k;
            const float2* __restrict__ col0 = s_p0 + lc * CSTRIDE;
            float xs = (k == 0) ? xv.x : (k == 1) ? xv.y : (k == 2) ? xv.z : xv.w;
            float xc = __saturatef(xs);

            // uniform guess + two simple divergent retry loops (few lanes active)
            int b = __float2int_rd(xc * 32.f);
            b = min(b, NBINS - 1);
            float2 p0 = col0[b];
            float theta = (xc - p0.x) * p0.y;
            while (theta < 0.f && b > 0) {
                --b; p0 = col0[b]; theta = (xc - p0.x) * p0.y;
            }
            while (theta >= 1.f && b < NBINS - 1) {
                ++b; p0 = col0[b]; theta = (xc - p0.x) * p0.y;
            }

            const float4 pc = s_pC[lc * CSTRIDE + b];

            float omt    = 1.f - theta;
            float t1m    = theta * omt;
            float th2    = theta * theta;
            float h      = pc.y;
            float delta  = h * p0.y;        // h * invw
            float delta2 = delta * delta;
            float dd0 = pc.z, dd1 = pc.w;

            float num  = h * fmaf(delta, th2, dd0 * t1m);
            float den  = fmaf(dd0 + dd1 - 2.f * delta, t1m, delta);
            float rden = __fdividef(1.f, den);
            float yin  = fmaf(num, rden, pc.x);

            float dnum = delta2 * fmaf(dd1, th2, fmaf(2.f * delta, t1m, dd0 * omt * omt));
            float lin  = __logf(dnum * rden * rden);

            bool inside = (xs >= 0.f) && (xs <= 1.f);
            yv[k] = inside ? yin : xs;
            lv[k] = inside ? lin : 0.f;
        }
        *(float4*)(outY + idx) = make_float4(yv[0], yv[1], yv[2], yv[3]);
        *(float4*)(outL + idx) = make_float4(lv[0], lv[1], lv[2], lv[3]);
    }
}

extern "C" void kernel_launch(void* const* d_in, const int* in_sizes, int n_in,
                              void* d_out, int out_size) {
    const float* x      = (const float*)d_in[0];
    const float* width  = (const float*)d_in[1];
    const float* height = (const float*)d_in[2];
    const float* deriv  = (const float*)d_in[3];
    float* out = (float*)d_out;

    const int B = in_sizes[0] / DIM;

    spline_precompute_kernel<<<DIM / 4, 128>>>(width, height, deriv);

    dim3 grid(148, DIM / CT);   // 1184 blocks = 148 SMs x 8 blocks (full thread wave)
    spline_main_kernel<<<grid, 256>>>(x, out, B);
}